// round 5
// baseline (speedup 1.0000x reference)
#include <cuda_runtime.h>
#include <cuda_bf16.h>

// Problem shape (fixed by the dataset)
#define BATCH 128
#define SEQLEN 1024
#define TAG 128

// Scratch (allocation-free rule: __device__ globals)
__device__ float g_logZ[BATCH];
__device__ float g_score[BATCH];

// ---------------- packed f32x2 helpers (Blackwell FFMA2) ----------------
__device__ __forceinline__ unsigned long long pack_f32x2(float lo, float hi) {
    unsigned long long r;
    asm("mov.b64 %0, {%1, %2};" : "=l"(r) : "f"(lo), "f"(hi));
    return r;
}
__device__ __forceinline__ void unpack_f32x2(float& lo, float& hi, unsigned long long v) {
    asm("mov.b64 {%0, %1}, %2;" : "=f"(lo), "=f"(hi) : "l"(v));
}
__device__ __forceinline__ unsigned long long fma2(unsigned long long a,
                                                   unsigned long long b,
                                                   unsigned long long c) {
    unsigned long long d;
    asm("fma.rn.f32x2 %0, %1, %2, %3;" : "=l"(d) : "l"(a), "l"(b), "l"(c));
    return d;
}
__device__ __forceinline__ unsigned long long add2(unsigned long long a,
                                                   unsigned long long b) {
    unsigned long long d;
    asm("add.rn.f32x2 %0, %1, %2;" : "=l"(d) : "l"(a), "l"(b));
    return d;
}

// Named barrier over one 128-thread half (ids 1 and 2). Keeps the two
// co-resident recurrences' barriers independent so their chains interleave.
__device__ __forceinline__ void half_sync(int barid) {
    asm volatile("bar.sync %0, %1;" :: "r"(barid), "r"(128) : "memory");
}

// ---------------- one exp-domain recurrence step --------------------------
// SLOT: prefetch ring slot. BUF: alpha double-buffer. RENORM: power-of-2
// renormalization this step (once per 4 steps; growth/shrink between renorms
// stays within [2^-40, 2^60] — fp32-safe, and the rescale itself is exact).
template <int SLOT, int BUF, bool RENORM>
__device__ __forceinline__ void crf_step(
    int i, int t, int barid, float& alpha, int& kacc,
    float (&eyp)[4], float (&mr)[4],
    const float* __restrict__ yprow, const float* __restrict__ mrow,
    const unsigned long long (&ea2)[64],
    float (*pb)[TAG], float* sb)
{
    // publish alpha (and the representative lane on renorm steps) — 1 barrier.
    pb[BUF][t] = alpha;
    if (RENORM && t == 0) sb[0] = alpha;
    half_sync(barid);

    float invc = 1.0f;
    if (RENORM) {
        // exact power-of-2 rescale putting repr into [1,2); pure ALU.
        int kb = (__float_as_int(sb[0]) >> 23) & 0xff;
        invc = __int_as_float((254 - kb) << 23);
        kacc += 127 - kb;
    }

    // prefetch row i+4 into this slot (consumed 4 steps from now); exp is
    // computed here, entirely off the recurrence's serial chain.
    float eyp_n = 0.0f, m_n = 1.0f;
    if (i + 4 < SEQLEN) {
        eyp_n = __expf(__ldg(yprow + (i + 4) * TAG));
        m_n   = __ldg(mrow + (i + 4));
    }

    // 128-wide dot: s_t = sum_u alpha[u] * e^{A[u][t]}, EA resident in regs.
    unsigned long long acc0 = 0ull, acc1 = 0ull, acc2 = 0ull, acc3 = 0ull;
    const ulonglong2* pp = reinterpret_cast<const ulonglong2*>(&pb[BUF][0]);
#pragma unroll
    for (int k = 0; k < 16; k++) {
        ulonglong2 v0 = pp[2 * k];
        ulonglong2 v1 = pp[2 * k + 1];
        acc0 = fma2(v0.x, ea2[4 * k + 0], acc0);
        acc1 = fma2(v0.y, ea2[4 * k + 1], acc1);
        acc2 = fma2(v1.x, ea2[4 * k + 2], acc2);
        acc3 = fma2(v1.y, ea2[4 * k + 3], acc3);
    }
    unsigned long long accA = add2(add2(acc0, acc1), add2(acc2, acc3));
    float slo, shi;
    unpack_f32x2(slo, shi, accA);
    float s = slo + shi;

    // masked update (mask is {0,1}); on renorm steps both branches carry invc.
    float cand = s * eyp[SLOT];
    if (RENORM) {
        alpha = (mr[SLOT] > 0.5f) ? cand * invc : alpha * invc;
    } else {
        alpha = (mr[SLOT] > 0.5f) ? cand : alpha;
    }
    eyp[SLOT] = eyp_n;
    mr[SLOT]  = m_n;
}

// ---------------- forward (log_Z) kernel: 2 batches per CTA ----------------
// 256 threads = two independent 128-thread recurrences. Warps 0-3 = batch A,
// warps 4-7 = batch B; wid%4 puts one warp of EACH batch on every SMSP, and
// named barriers keep their dependency chains decoupled so they interleave.
__global__ void __launch_bounds__(256, 1)
crf_forward_kernel(const float* __restrict__ y_pred,
                   const float* __restrict__ mask,
                   const float* __restrict__ A)
{
    const int tid = threadIdx.x;
    const int sub = tid >> 7;            // which batch half
    const int t   = tid & (TAG - 1);     // tag index
    const int b   = (blockIdx.x << 1) | sub;
    const int barid = sub + 1;           // named barrier id for this half

    __shared__ __align__(16) float pbuf[2][2][TAG];  // [sub][buf][tag]
    __shared__ float sbroad[2][1];
    float (*pb)[TAG] = pbuf[sub];
    float* sb = sbroad[sub];

    // ---- load e^{A} column t into registers (A in [-0.1,0.1]: no shift) ----
    unsigned long long ea2[64];
#pragma unroll
    for (int k = 0; k < 64; k++) {
        float e0 = __expf(__ldg(A + (2 * k)     * TAG + t));
        float e1 = __expf(__ldg(A + (2 * k + 1) * TAG + t));
        ea2[k] = pack_f32x2(e0, e1);
    }

    const float* yprow = y_pred + (size_t)b * SEQLEN * TAG + t;
    const float* mrow  = mask + (size_t)b * SEQLEN;

    // ---- init: alpha = e^{y_pred[b,0,:]} ----
    float alpha = __expf(__ldg(yprow));
    int kacc = 0;

    // prefetch rows 1..4 (with exp applied)
    float eyp[4], mr[4];
#pragma unroll
    for (int j = 0; j < 4; j++) {
        eyp[j] = __expf(__ldg(yprow + (1 + j) * TAG));
        mr[j]  = __ldg(mrow + (1 + j));
    }

    // ---- main scan: steps i = 1 .. SEQLEN-1 (1023 steps = 255*4 + 3) ----
    int i = 1;
    for (; i + 3 < SEQLEN; i += 4) {
        crf_step<0, 1, true >(i,     t, barid, alpha, kacc, eyp, mr, yprow, mrow, ea2, pb, sb);
        crf_step<1, 0, false>(i + 1, t, barid, alpha, kacc, eyp, mr, yprow, mrow, ea2, pb, sb);
        crf_step<2, 1, false>(i + 2, t, barid, alpha, kacc, eyp, mr, yprow, mrow, ea2, pb, sb);
        crf_step<3, 0, false>(i + 3, t, barid, alpha, kacc, eyp, mr, yprow, mrow, ea2, pb, sb);
    }
    // remainder: i = 1021, 1022, 1023
    crf_step<0, 1, true >(i,     t, barid, alpha, kacc, eyp, mr, yprow, mrow, ea2, pb, sb);
    crf_step<1, 0, false>(i + 1, t, barid, alpha, kacc, eyp, mr, yprow, mrow, ea2, pb, sb);
    crf_step<2, 1, false>(i + 2, t, barid, alpha, kacc, eyp, mr, yprow, mrow, ea2, pb, sb);

    // ---- final: logZ = log(sum_t alpha) - kacc*ln2 (per batch half) ----
    pb[0][t] = alpha;
    half_sync(barid);
    if (t < 32) {
        float v = pb[0][t] + pb[0][t + 32] + pb[0][t + 64] + pb[0][t + 96];
#pragma unroll
        for (int o = 16; o > 0; o >>= 1)
            v += __shfl_xor_sync(0xffffffffu, v, o);
        if (t == 0)
            g_logZ[b] = logf(v) - (float)kacc * 0.69314718055994530942f;
    }
}

// ---------------- score kernel: 1 CTA per batch ----------------
// y_true arrives as int32 under JAX's default x64-disabled config; handle a
// genuine little-endian int64 layout too by runtime detection (odd 32-bit
// words of the first 128 entries all zero <=> int64, since tags are 0..127).
__global__ void __launch_bounds__(128, 1)
crf_score_kernel(const float* __restrict__ y_pred,
                 const int* __restrict__ y_true32,
                 const float* __restrict__ mask,
                 const float* __restrict__ A)
{
    const int b = blockIdx.x;
    const int t = threadIdx.x;

    // dtype detection, parallel across 128 threads (same verdict everywhere;
    // benign race: any nonzero odd word clears the flag)
    __shared__ int s_is64;
    if (t == 0) s_is64 = 1;
    __syncthreads();
    if (y_true32[2 * t + 1] != 0) s_is64 = 0;
    __syncthreads();
    const int stride = s_is64 ? 2 : 1;
    const int* yt = y_true32 + (size_t)b * SEQLEN * stride;

    const float* mrow = mask + (size_t)b * SEQLEN;
    const float* yprow = y_pred + (size_t)b * SEQLEN * TAG;

    float acc = 0.0f;
    for (int s = t; s < SEQLEN; s += 128) {
        int tag = yt[s * stride] & (TAG - 1);   // tags are 0..127; mask is safety net
        float m = mrow[s];
        acc += yprow[(size_t)s * TAG + tag] * m;
        if (s + 1 < SEQLEN) {
            int tag2 = yt[(s + 1) * stride] & (TAG - 1);
            float m2 = mrow[s + 1];
            acc += A[tag * TAG + tag2] * m * m2;
        }
    }
    __shared__ float red[128];
    red[t] = acc;
    __syncthreads();
    if (t < 32) {
        float v = red[t] + red[t + 32] + red[t + 64] + red[t + 96];
#pragma unroll
        for (int o = 16; o > 0; o >>= 1)
            v += __shfl_xor_sync(0xffffffffu, v, o);
        if (t == 0) g_score[b] = v;
    }
}

// ---------------- final mean kernel ----------------
__global__ void __launch_bounds__(128, 1)
crf_final_kernel(float* __restrict__ out)
{
    const int t = threadIdx.x;
    float v = g_logZ[t] - g_score[t];
    __shared__ float red[128];
    red[t] = v;
    __syncthreads();
    if (t < 32) {
        float s = red[t] + red[t + 32] + red[t + 64] + red[t + 96];
#pragma unroll
        for (int o = 16; o > 0; o >>= 1)
            s += __shfl_xor_sync(0xffffffffu, s, o);
        if (t == 0) out[0] = s * (1.0f / (float)BATCH);
    }
}

// ---------------- launch ----------------
extern "C" void kernel_launch(void* const* d_in, const int* in_sizes, int n_in,
                              void* d_out, int out_size)
{
    // Identify inputs by element count:
    //   y_pred: BATCH*SEQLEN*TAG, A: TAG*TAG, y_true & mask: BATCH*SEQLEN
    //   (y_true precedes mask in metadata/dict order).
    const float* y_pred = nullptr;
    const float* A = nullptr;
    const int* y_true = nullptr;
    const float* mask = nullptr;
    for (int i = 0; i < n_in; i++) {
        long long sz = in_sizes[i];
        if (sz == (long long)BATCH * SEQLEN * TAG) {
            y_pred = (const float*)d_in[i];
        } else if (sz == (long long)TAG * TAG) {
            A = (const float*)d_in[i];
        } else if (sz == (long long)BATCH * SEQLEN) {
            if (!y_true) y_true = (const int*)d_in[i];
            else mask = (const float*)d_in[i];
        }
    }

    crf_forward_kernel<<<BATCH / 2, 256>>>(y_pred, mask, A);
    crf_score_kernel<<<BATCH, 128>>>(y_pred, y_true, mask, A);
    crf_final_kernel<<<1, 128>>>((float*)d_out);
}

// round 6
// speedup vs baseline: 1.9236x; 1.9236x over previous
#include <cuda_runtime.h>
#include <cuda_bf16.h>

// Problem shape (fixed by the dataset)
#define BATCH 128
#define SEQLEN 1024
#define TAG 128
#define MID 512           // forward covers steps 1..MID, backward MID+1..SEQLEN-1

// Scratch (allocation-free rule: __device__ globals)
__device__ float g_logZ[BATCH];
__device__ float g_score[BATCH];

// ---------------- packed f32x2 helpers (Blackwell FFMA2) ----------------
__device__ __forceinline__ unsigned long long pack_f32x2(float lo, float hi) {
    unsigned long long r;
    asm("mov.b64 %0, {%1, %2};" : "=l"(r) : "f"(lo), "f"(hi));
    return r;
}
__device__ __forceinline__ void unpack_f32x2(float& lo, float& hi, unsigned long long v) {
    asm("mov.b64 {%0, %1}, %2;" : "=f"(lo), "=f"(hi) : "l"(v));
}
__device__ __forceinline__ unsigned long long fma2(unsigned long long a,
                                                   unsigned long long b,
                                                   unsigned long long c) {
    unsigned long long d;
    asm("fma.rn.f32x2 %0, %1, %2, %3;" : "=l"(d) : "l"(a), "l"(b), "l"(c));
    return d;
}
__device__ __forceinline__ unsigned long long add2(unsigned long long a,
                                                   unsigned long long b) {
    unsigned long long d;
    asm("add.rn.f32x2 %0, %1, %2;" : "=l"(d) : "l"(a), "l"(b));
    return d;
}

// Named barrier over one 128-thread half (ids 1 and 2).
__device__ __forceinline__ void half_sync(int barid) {
    asm volatile("bar.sync %0, %1;" :: "r"(barid), "r"(128) : "memory");
}

// shared 128-wide dot: s_t = sum_u vec[u] * w2[u/2] (packed), vec in smem.
__device__ __forceinline__ float dot128(const float* __restrict__ vec,
                                        const unsigned long long (&w2)[64]) {
    unsigned long long acc0 = 0ull, acc1 = 0ull, acc2 = 0ull, acc3 = 0ull;
    const ulonglong2* pp = reinterpret_cast<const ulonglong2*>(vec);
#pragma unroll
    for (int k = 0; k < 16; k++) {
        ulonglong2 v0 = pp[2 * k];
        ulonglong2 v1 = pp[2 * k + 1];
        acc0 = fma2(v0.x, w2[4 * k + 0], acc0);
        acc1 = fma2(v0.y, w2[4 * k + 1], acc1);
        acc2 = fma2(v1.x, w2[4 * k + 2], acc2);
        acc3 = fma2(v1.y, w2[4 * k + 3], acc3);
    }
    unsigned long long accA = add2(add2(acc0, acc1), add2(acc2, acc3));
    float slo, shi;
    unpack_f32x2(slo, shi, accA);
    return slo + shi;
}

// ---------------- forward step: alpha' = m*(alpha@EA)*ey + (1-m)*alpha ------
// RENORM: exact power-of-2 rescale once per 4 steps (range-safe: growth stays
// within [2^-60, 2^60] between renorms).
template <int SLOT, int BUF, bool RENORM>
__device__ __forceinline__ void fwd_step(
    int i, int t, float& alpha, int& kacc,
    float (&eyp)[4], float (&mr)[4],
    const float* __restrict__ yprow, const float* __restrict__ mrow,
    const unsigned long long (&ea2)[64],
    float (*pb)[TAG], float* sb)
{
    pb[BUF][t] = alpha;
    if (RENORM && t == 0) sb[0] = alpha;
    half_sync(1);

    float invc = 1.0f;
    if (RENORM) {
        int kb = (__float_as_int(sb[0]) >> 23) & 0xff;
        invc = __int_as_float((254 - kb) << 23);
        kacc += 127 - kb;
    }

    // prefetch row i+4 (consumed 4 steps from now); exp off the serial chain
    float eyp_n = 0.0f, m_n = 1.0f;
    if (i + 4 <= MID) {
        eyp_n = __expf(__ldg(yprow + (i + 4) * TAG));
        m_n   = __ldg(mrow + (i + 4));
    }

    float s = dot128(&pb[BUF][0], ea2);

    float cand = s * eyp[SLOT];
    if (RENORM) {
        alpha = (mr[SLOT] > 0.5f) ? cand * invc : alpha * invc;
    } else {
        alpha = (mr[SLOT] > 0.5f) ? cand : alpha;
    }
    eyp[SLOT] = eyp_n;
    mr[SLOT]  = m_n;
}

// ---------------- backward step: beta' = m*(EA@(ey.*beta)) + (1-m)*beta -----
// publishes c = ey.*beta; thread t holds EA row t packed in ear2.
template <int SLOT, int BUF, bool RENORM>
__device__ __forceinline__ void bwd_step(
    int i, int t, float& beta, int& kacc,
    float (&eyp)[4], float (&mr)[4],
    const float* __restrict__ yprow, const float* __restrict__ mrow,
    const unsigned long long (&ear2)[64],
    float (*pb)[TAG], float* sb)
{
    float c = beta * eyp[SLOT];
    pb[BUF][t] = c;
    if (RENORM && t == 0) sb[0] = c;
    half_sync(2);

    float invc = 1.0f;
    if (RENORM) {
        int kb = (__float_as_int(sb[0]) >> 23) & 0xff;
        invc = __int_as_float((254 - kb) << 23);
        kacc += 127 - kb;
    }

    // prefetch row i-4 (consumed 4 steps from now)
    float eyp_n = 0.0f, m_n = 1.0f;
    if (i - 4 > MID) {
        eyp_n = __expf(__ldg(yprow + (i - 4) * TAG));
        m_n   = __ldg(mrow + (i - 4));
    }

    float s = dot128(&pb[BUF][0], ear2);

    if (RENORM) {
        beta = ((mr[SLOT] > 0.5f) ? s : beta) * invc;
    } else {
        beta = (mr[SLOT] > 0.5f) ? s : beta;
    }
    eyp[SLOT] = eyp_n;
    mr[SLOT]  = m_n;
}

// ---------------- bidirectional logZ kernel: 1 CTA (256 thr) per batch -----
// Warps 0-3: forward recurrence (EA columns in regs). Warps 4-7: backward
// (EA rows in regs). Halves are decoupled via named barriers; serial depth
// drops from 1023 to 512 steps. Z = sum_t a_mid[t] * b_mid[t].
__global__ void __launch_bounds__(256, 1)
crf_forward_kernel(const float* __restrict__ y_pred,
                   const float* __restrict__ mask,
                   const float* __restrict__ A)
{
    const int tid = threadIdx.x;
    const int sub = tid >> 7;            // 0 = forward, 1 = backward
    const int t   = tid & (TAG - 1);
    const int b   = blockIdx.x;

    __shared__ __align__(16) float pbuf[2][2][TAG];  // [sub][buf][tag]
    __shared__ float sbroad[2][1];
    __shared__ int   skacc[2];
    float (*pb)[TAG] = pbuf[sub];
    float* sb = sbroad[sub];

    const float* yprow = y_pred + (size_t)b * SEQLEN * TAG + t;
    const float* mrow  = mask + (size_t)b * SEQLEN;

    if (sub == 0) {
        // ===================== FORWARD half: steps 1..512 ====================
        unsigned long long ea2[64];           // EA column t, packed along u
#pragma unroll
        for (int k = 0; k < 64; k++) {
            float e0 = __expf(__ldg(A + (2 * k)     * TAG + t));
            float e1 = __expf(__ldg(A + (2 * k + 1) * TAG + t));
            ea2[k] = pack_f32x2(e0, e1);
        }

        float alpha = __expf(__ldg(yprow));   // alpha_0 = e^{yp_0}
        int kacc = 0;

        float eyp[4], mr[4];
#pragma unroll
        for (int j = 0; j < 4; j++) {
            eyp[j] = __expf(__ldg(yprow + (1 + j) * TAG));
            mr[j]  = __ldg(mrow + (1 + j));
        }

        // 512 steps = 128 groups of 4, exactly
        for (int i = 1; i + 3 <= MID; i += 4) {
            fwd_step<0, 1, true >(i,     t, alpha, kacc, eyp, mr, yprow, mrow, ea2, pb, sb);
            fwd_step<1, 0, false>(i + 1, t, alpha, kacc, eyp, mr, yprow, mrow, ea2, pb, sb);
            fwd_step<2, 1, false>(i + 2, t, alpha, kacc, eyp, mr, yprow, mrow, ea2, pb, sb);
            fwd_step<3, 0, false>(i + 3, t, alpha, kacc, eyp, mr, yprow, mrow, ea2, pb, sb);
        }

        pb[0][t] = alpha;                     // publish a_mid
        if (t == 0) skacc[0] = kacc;
    } else {
        // ===================== BACKWARD half: steps 1023..513 ===============
        unsigned long long ear2[64];          // EA row t, packed along u
        const float* arow = A + (size_t)t * TAG;
#pragma unroll
        for (int k = 0; k < 64; k++) {
            float e0 = __expf(__ldg(arow + 2 * k));
            float e1 = __expf(__ldg(arow + 2 * k + 1));
            ear2[k] = pack_f32x2(e0, e1);
        }

        float beta = 1.0f;                    // b_{1023} = 1
        int kacc = 0;

        float eyp[4], mr[4];
#pragma unroll
        for (int j = 0; j < 4; j++) {
            eyp[j] = __expf(__ldg(yprow + (SEQLEN - 1 - j) * TAG));
            mr[j]  = __ldg(mrow + (SEQLEN - 1 - j));
        }

        // 511 steps: 127 groups of 4 (i = 1023 .. 516), remainder 515,514,513
        int i = SEQLEN - 1;
        for (; i - 3 > MID + 3; i -= 4) {
            bwd_step<0, 1, true >(i,     t, beta, kacc, eyp, mr, yprow, mrow, ear2, pb, sb);
            bwd_step<1, 0, false>(i - 1, t, beta, kacc, eyp, mr, yprow, mrow, ear2, pb, sb);
            bwd_step<2, 1, false>(i - 2, t, beta, kacc, eyp, mr, yprow, mrow, ear2, pb, sb);
            bwd_step<3, 0, false>(i - 3, t, beta, kacc, eyp, mr, yprow, mrow, ear2, pb, sb);
        }
        // i == 515 here
        bwd_step<0, 1, true >(i,     t, beta, kacc, eyp, mr, yprow, mrow, ear2, pb, sb);
        bwd_step<1, 0, false>(i - 1, t, beta, kacc, eyp, mr, yprow, mrow, ear2, pb, sb);
        bwd_step<2, 1, false>(i - 2, t, beta, kacc, eyp, mr, yprow, mrow, ear2, pb, sb);

        pb[0][t] = beta;                      // publish b_mid
        if (t == 0) skacc[1] = kacc;
    }

    __syncthreads();   // join halves

    // ---- Z = sum_t a[t]*b[t];  logZ = log(Z) - (kf+kb)*ln2 ----
    if (tid < 32) {
        float v = 0.0f;
#pragma unroll
        for (int j = 0; j < 4; j++) {
            int idx = tid + 32 * j;
            v += pbuf[0][0][idx] * pbuf[1][0][idx];
        }
#pragma unroll
        for (int o = 16; o > 0; o >>= 1)
            v += __shfl_xor_sync(0xffffffffu, v, o);
        if (tid == 0) {
            int ktot = skacc[0] + skacc[1];
            g_logZ[b] = logf(v) - (float)ktot * 0.69314718055994530942f;
        }
    }
}

// ---------------- score kernel: 1 CTA per batch ----------------
// y_true arrives as int32 under JAX's default x64-disabled config; handle a
// genuine little-endian int64 layout too by runtime detection (odd 32-bit
// words of the first 128 entries all zero <=> int64, since tags are 0..127).
__global__ void __launch_bounds__(128, 1)
crf_score_kernel(const float* __restrict__ y_pred,
                 const int* __restrict__ y_true32,
                 const float* __restrict__ mask,
                 const float* __restrict__ A)
{
    const int b = blockIdx.x;
    const int t = threadIdx.x;

    __shared__ int s_is64;
    if (t == 0) s_is64 = 1;
    __syncthreads();
    if (y_true32[2 * t + 1] != 0) s_is64 = 0;
    __syncthreads();
    const int stride = s_is64 ? 2 : 1;
    const int* yt = y_true32 + (size_t)b * SEQLEN * stride;

    const float* mrow = mask + (size_t)b * SEQLEN;
    const float* yprow = y_pred + (size_t)b * SEQLEN * TAG;

    float acc = 0.0f;
    for (int s = t; s < SEQLEN; s += 128) {
        int tag = yt[s * stride] & (TAG - 1);
        float m = mrow[s];
        acc += yprow[(size_t)s * TAG + tag] * m;
        if (s + 1 < SEQLEN) {
            int tag2 = yt[(s + 1) * stride] & (TAG - 1);
            float m2 = mrow[s + 1];
            acc += A[tag * TAG + tag2] * m * m2;
        }
    }
    __shared__ float red[128];
    red[t] = acc;
    __syncthreads();
    if (t < 32) {
        float v = red[t] + red[t + 32] + red[t + 64] + red[t + 96];
#pragma unroll
        for (int o = 16; o > 0; o >>= 1)
            v += __shfl_xor_sync(0xffffffffu, v, o);
        if (t == 0) g_score[b] = v;
    }
}

// ---------------- final mean kernel ----------------
__global__ void __launch_bounds__(128, 1)
crf_final_kernel(float* __restrict__ out)
{
    const int t = threadIdx.x;
    float v = g_logZ[t] - g_score[t];
    __shared__ float red[128];
    red[t] = v;
    __syncthreads();
    if (t < 32) {
        float s = red[t] + red[t + 32] + red[t + 64] + red[t + 96];
#pragma unroll
        for (int o = 16; o > 0; o >>= 1)
            s += __shfl_xor_sync(0xffffffffu, s, o);
        if (t == 0) out[0] = s * (1.0f / (float)BATCH);
    }
}

// ---------------- launch ----------------
extern "C" void kernel_launch(void* const* d_in, const int* in_sizes, int n_in,
                              void* d_out, int out_size)
{
    const float* y_pred = nullptr;
    const float* A = nullptr;
    const int* y_true = nullptr;
    const float* mask = nullptr;
    for (int i = 0; i < n_in; i++) {
        long long sz = in_sizes[i];
        if (sz == (long long)BATCH * SEQLEN * TAG) {
            y_pred = (const float*)d_in[i];
        } else if (sz == (long long)TAG * TAG) {
            A = (const float*)d_in[i];
        } else if (sz == (long long)BATCH * SEQLEN) {
            if (!y_true) y_true = (const int*)d_in[i];
            else mask = (const float*)d_in[i];
        }
    }

    crf_forward_kernel<<<BATCH, 256>>>(y_pred, mask, A);
    crf_score_kernel<<<BATCH, 128>>>(y_pred, y_true, mask, A);
    crf_final_kernel<<<1, 128>>>((float*)d_out);
}